// round 12
// baseline (speedup 1.0000x reference)
#include <cuda_runtime.h>
#include <cuda_fp16.h>
#include <math.h>
#include <stdint.h>
#include <string.h>

#define N_ITERS 12
#define NB 4
#define NH 384
#define NW 512
#define HW (NH * NW)
#define NTHREADS 256
#define PIX_PER_THREAD 4
#define PIX_PER_BLK (NTHREADS * PIX_PER_THREAD)   // 1024
#define GRID_X (HW / PIX_PER_BLK)                 // 192
#define TOT_BLOCKS (GRID_X * NB)                  // 768

// frame1 packed as half4 (c0,c1,c2,0), [B][H][W]. 6.3 MB. 4096B-aligned so
// each batch slice (384 rows * 4096B pitch) is texture-alignment clean.
__device__ __align__(4096) ushort4 g_f1h[NB * HW];

__device__ float g_sums[N_ITERS];        // zero-init at load; reset by last block
__device__ unsigned int g_ticket = 0;    // reset by last block

struct TexPack { cudaTextureObject_t t[NB]; };

// ---- Texture objects over the packed scratch. Created ONCE, outside graph
// capture: at static-init if possible, else on the first (uncaptured)
// correctness call. No device memory is allocated. ----
static TexPack g_texs;
static bool g_tex_ready = false;

static void create_texs() {
    void* scratch = nullptr;
    if (cudaGetSymbolAddress(&scratch, g_f1h) != cudaSuccess || scratch == nullptr)
        return;  // runtime not ready yet; retry on first call
    cudaChannelFormatDesc cdesc =
        cudaCreateChannelDesc(16, 16, 16, 16, cudaChannelFormatKindFloat);
    bool ok = true;
    for (int b = 0; b < NB; b++) {
        cudaResourceDesc rdesc;
        memset(&rdesc, 0, sizeof(rdesc));
        rdesc.resType = cudaResourceTypePitch2D;
        rdesc.res.pitch2D.devPtr = (char*)scratch + (size_t)b * HW * sizeof(ushort4);
        rdesc.res.pitch2D.desc = cdesc;
        rdesc.res.pitch2D.width = NW;
        rdesc.res.pitch2D.height = NH;
        rdesc.res.pitch2D.pitchInBytes = NW * sizeof(ushort4);   // 4096

        cudaTextureDesc tdesc;
        memset(&tdesc, 0, sizeof(tdesc));
        tdesc.addressMode[0] = cudaAddressModeBorder;   // OOB texel -> 0
        tdesc.addressMode[1] = cudaAddressModeBorder;
        tdesc.filterMode = cudaFilterModeLinear;
        tdesc.readMode = cudaReadModeElementType;
        tdesc.normalizedCoords = 0;

        if (cudaCreateTextureObject(&g_texs.t[b], &rdesc, &tdesc, nullptr)
            != cudaSuccess) ok = false;
    }
    g_tex_ready = ok;
}

namespace { struct TexInit { TexInit() { create_texs(); } } s_texinit; }

// ---- Prolog: pack planar fp32 frame1 -> interleaved half4 ----
__global__ __launch_bounds__(256) void pack_kernel(const float* __restrict__ f1) {
    const int idx = blockIdx.x * 256 + threadIdx.x;
    if (idx >= NB * HW) return;
    const int b = idx / HW;
    const int p = idx - b * HW;
    const float* base = f1 + (size_t)b * 3 * HW + p;
    ushort4 v;
    v.x = __half_as_ushort(__float2half_rn(base[0]));
    v.y = __half_as_ushort(__float2half_rn(base[HW]));
    v.z = __half_as_ushort(__float2half_rn(base[2 * HW]));
    v.w = 0;
    g_f1h[idx] = v;
}

// ---- Main: 12 fused iterations x 4 pixels/thread, bilinear via texture HW.
// All global loads are LDG.128. ----
__global__ __launch_bounds__(NTHREADS) void warp_psnr_kernel(
    TexPack texs,
    const float* __restrict__ flow,
    const float* __restrict__ frame2,
    float* __restrict__ out)
{
    const int pix0 = blockIdx.x * PIX_PER_BLK + threadIdx.x * PIX_PER_THREAD;
    const int b = blockIdx.y;
    const cudaTextureObject_t tex = texs.t[b];

    // 4 consecutive pixels share a row (PIX_PER_THREAD=4 aligned, W=512).
    const int h = pix0 >> 9;
    const int w = pix0 & 511;
    const float hf = (float)h + 0.5f;       // align_corners pixel -> texel
    const float wf = (float)w + 0.5f;

    const float* f2 = frame2 + (size_t)b * 3 * HW + pix0;
    const float4 r2x = *(const float4*)(f2);
    const float4 r2y = *(const float4*)(f2 + HW);
    const float4 r2z = *(const float4*)(f2 + 2 * HW);

    const float* flp = flow + (size_t)b * 2 * HW + pix0;

    float sums[N_ITERS];

    #pragma unroll
    for (int i = 0; i < N_ITERS; i++) {
        const float4 fy = *(const float4*)(flp + (size_t)i * NB * 2 * HW);
        const float4 fx = *(const float4*)(flp + (size_t)i * NB * 2 * HW + HW);

        // 4 independent texture fetches -> tex latency covered by ILP.
        const float4 e0 = tex2D<float4>(tex, wf + 0.5f * 0 + fx.x + 0.0f, hf + fy.x);
        const float4 e1 = tex2D<float4>(tex, wf + 1.0f + fx.y, hf + fy.y);
        const float4 e2 = tex2D<float4>(tex, wf + 2.0f + fx.z, hf + fy.z);
        const float4 e3 = tex2D<float4>(tex, wf + 3.0f + fx.w, hf + fy.w);

        float s;
        float d;
        d = e0.x - r2x.x; s  = d * d;
        d = e0.y - r2y.x; s  = fmaf(d, d, s);
        d = e0.z - r2z.x; s  = fmaf(d, d, s);
        d = e1.x - r2x.y; s  = fmaf(d, d, s);
        d = e1.y - r2y.y; s  = fmaf(d, d, s);
        d = e1.z - r2z.y; s  = fmaf(d, d, s);
        d = e2.x - r2x.z; s  = fmaf(d, d, s);
        d = e2.y - r2y.z; s  = fmaf(d, d, s);
        d = e2.z - r2z.z; s  = fmaf(d, d, s);
        d = e3.x - r2x.w; s  = fmaf(d, d, s);
        d = e3.y - r2y.w; s  = fmaf(d, d, s);
        d = e3.z - r2z.w; s  = fmaf(d, d, s);
        sums[i] = s;
    }

    // ---- Block reduction: shuffle -> shared -> 12 global atomics ----
    __shared__ float red[N_ITERS][NTHREADS / 32];
    __shared__ bool s_last;
    const int tid  = threadIdx.x;
    const int lane = tid & 31;
    const int wid  = tid >> 5;

    #pragma unroll
    for (int i = 0; i < N_ITERS; i++) {
        float s = sums[i];
        s += __shfl_down_sync(0xffffffffu, s, 16);
        s += __shfl_down_sync(0xffffffffu, s, 8);
        s += __shfl_down_sync(0xffffffffu, s, 4);
        s += __shfl_down_sync(0xffffffffu, s, 2);
        s += __shfl_down_sync(0xffffffffu, s, 1);
        if (lane == 0) red[i][wid] = s;
    }
    __syncthreads();

    if (tid < N_ITERS) {
        float t = 0.0f;
        #pragma unroll
        for (int ww = 0; ww < NTHREADS / 32; ww++) t += red[tid][ww];
        atomicAdd(&g_sums[tid], t);
    }
    __syncthreads();

    // ---- Last block computes the loss and resets state for graph replay ----
    if (tid == 0) {
        __threadfence();
        const unsigned int ticket = atomicAdd(&g_ticket, 1u);
        s_last = (ticket == TOT_BLOCKS - 1);
    }
    __syncthreads();

    if (s_last && tid == 0) {
        const float inv_n = 1.0f / (float)(NB * 3 * HW);
        float loss = 0.0f;
        #pragma unroll
        for (int k = 0; k < N_ITERS; k++) {
            const float ssum = atomicAdd(&g_sums[k], 0.0f);   // coherent read
            const float mse = ssum * inv_n;
            const float psnr = -10.0f * log10f(mse);
            const float wgt = powf(0.85f, (float)(N_ITERS - k));
            loss += psnr * wgt;
        }
        out[0] = -loss;
        #pragma unroll
        for (int k = 0; k < N_ITERS; k++) g_sums[k] = 0.0f;
        g_ticket = 0u;
        __threadfence();
    }
}

extern "C" void kernel_launch(void* const* d_in, const int* in_sizes, int n_in,
                              void* d_out, int out_size) {
    const float* flow   = (const float*)d_in[0];  // [12,4,2,384,512]
    const float* frame1 = (const float*)d_in[1];  // [4,3,384,512]
    const float* frame2 = (const float*)d_in[2];  // [4,3,384,512]
    float* out = (float*)d_out;
    (void)in_sizes; (void)n_in; (void)out_size;

    if (!g_tex_ready) create_texs();   // first (uncaptured) call only

    pack_kernel<<<(NB * HW + 255) / 256, 256>>>(frame1);

    dim3 grid(GRID_X, NB);
    warp_psnr_kernel<<<grid, NTHREADS>>>(g_texs, flow, frame2, out);
}

// round 13
// speedup vs baseline: 1.2283x; 1.2283x over previous
#include <cuda_runtime.h>
#include <cuda_fp16.h>
#include <math.h>
#include <stdint.h>
#include <string.h>

#define N_ITERS 12
#define NB 4
#define NH 384
#define NW 512
#define HW (NH * NW)
#define NTHREADS 256
#define PIX_PER_THREAD 2
#define PIX_PER_BLK (NTHREADS * PIX_PER_THREAD)   // 512
#define GRID_X (HW / PIX_PER_BLK)                 // 384
#define TOT_BLOCKS (GRID_X * NB)                  // 1536

// frame1 packed as half4 (c0,c1,c2,0), [B][H][W]. 6.3 MB. 4096B-aligned so
// each batch slice (384 rows * 4096B pitch) is texture-alignment clean.
__device__ __align__(4096) ushort4 g_f1h[NB * HW];

__device__ float g_sums[N_ITERS];        // zero-init at load; reset by last block
__device__ unsigned int g_ticket = 0;    // reset by last block

struct TexPack { cudaTextureObject_t t[NB]; };

// ---- Texture objects over the packed scratch. Created ONCE, outside graph
// capture: at static-init if possible, else on the first (uncaptured)
// correctness call. No device memory is allocated. ----
static TexPack g_texs;
static bool g_tex_ready = false;

static void create_texs() {
    void* scratch = nullptr;
    if (cudaGetSymbolAddress(&scratch, g_f1h) != cudaSuccess || scratch == nullptr)
        return;  // runtime not ready yet; retry on first call
    cudaChannelFormatDesc cdesc =
        cudaCreateChannelDesc(16, 16, 16, 16, cudaChannelFormatKindFloat);
    bool ok = true;
    for (int b = 0; b < NB; b++) {
        cudaResourceDesc rdesc;
        memset(&rdesc, 0, sizeof(rdesc));
        rdesc.resType = cudaResourceTypePitch2D;
        rdesc.res.pitch2D.devPtr = (char*)scratch + (size_t)b * HW * sizeof(ushort4);
        rdesc.res.pitch2D.desc = cdesc;
        rdesc.res.pitch2D.width = NW;
        rdesc.res.pitch2D.height = NH;
        rdesc.res.pitch2D.pitchInBytes = NW * sizeof(ushort4);   // 4096

        cudaTextureDesc tdesc;
        memset(&tdesc, 0, sizeof(tdesc));
        tdesc.addressMode[0] = cudaAddressModeBorder;   // OOB texel -> 0
        tdesc.addressMode[1] = cudaAddressModeBorder;
        tdesc.filterMode = cudaFilterModeLinear;
        tdesc.readMode = cudaReadModeElementType;
        tdesc.normalizedCoords = 0;

        if (cudaCreateTextureObject(&g_texs.t[b], &rdesc, &tdesc, nullptr)
            != cudaSuccess) ok = false;
    }
    g_tex_ready = ok;
}

namespace { struct TexInit { TexInit() { create_texs(); } } s_texinit; }

// ---- Prolog: pack planar fp32 frame1 -> interleaved half4 ----
__global__ __launch_bounds__(256) void pack_kernel(const float* __restrict__ f1) {
    const int idx = blockIdx.x * 256 + threadIdx.x;
    if (idx >= NB * HW) return;
    const int b = idx / HW;
    const int p = idx - b * HW;
    const float* base = f1 + (size_t)b * 3 * HW + p;
    ushort4 v;
    v.x = __half_as_ushort(__float2half_rn(base[0]));
    v.y = __half_as_ushort(__float2half_rn(base[HW]));
    v.z = __half_as_ushort(__float2half_rn(base[2 * HW]));
    v.w = 0;
    g_f1h[idx] = v;
}

// ---- Main: 12 fused iterations x 2 pixels/thread, bilinear via texture HW.
// Flow/frame2 loads are LDG.64; regs capped for >=6 blocks/SM. ----
__global__ __launch_bounds__(NTHREADS, 6) void warp_psnr_kernel(
    TexPack texs,
    const float* __restrict__ flow,
    const float* __restrict__ frame2,
    float* __restrict__ out)
{
    const int pix0 = blockIdx.x * PIX_PER_BLK + threadIdx.x * PIX_PER_THREAD;
    const int b = blockIdx.y;
    const cudaTextureObject_t tex = texs.t[b];

    // 2 consecutive pixels share a row (pix0 even, W=512).
    const int h = pix0 >> 9;
    const int w = pix0 & 511;
    const float hf = (float)h + 0.5f;       // align_corners pixel -> texel
    const float wf = (float)w + 0.5f;

    const float* f2 = frame2 + (size_t)b * 3 * HW + pix0;
    const float2 r2x = *(const float2*)(f2);
    const float2 r2y = *(const float2*)(f2 + HW);
    const float2 r2z = *(const float2*)(f2 + 2 * HW);

    const float* flp = flow + (size_t)b * 2 * HW + pix0;

    float sums[N_ITERS];

    #pragma unroll
    for (int i = 0; i < N_ITERS; i++) {
        const float2 fy = *(const float2*)(flp + (size_t)i * NB * 2 * HW);
        const float2 fx = *(const float2*)(flp + (size_t)i * NB * 2 * HW + HW);

        // 2 independent texture fetches; border mode reproduces
        // grid_sample(padding_mode='zeros') exactly.
        const float4 e0 = tex2D<float4>(tex, wf + fx.x, hf + fy.x);
        const float4 e1 = tex2D<float4>(tex, wf + 1.0f + fx.y, hf + fy.y);

        float s, d;
        d = e0.x - r2x.x; s = d * d;
        d = e0.y - r2y.x; s = fmaf(d, d, s);
        d = e0.z - r2z.x; s = fmaf(d, d, s);
        d = e1.x - r2x.y; s = fmaf(d, d, s);
        d = e1.y - r2y.y; s = fmaf(d, d, s);
        d = e1.z - r2z.y; s = fmaf(d, d, s);
        sums[i] = s;
    }

    // ---- Block reduction: shuffle -> shared -> 12 global atomics ----
    __shared__ float red[N_ITERS][NTHREADS / 32];
    __shared__ bool s_last;
    const int tid  = threadIdx.x;
    const int lane = tid & 31;
    const int wid  = tid >> 5;

    #pragma unroll
    for (int i = 0; i < N_ITERS; i++) {
        float s = sums[i];
        s += __shfl_down_sync(0xffffffffu, s, 16);
        s += __shfl_down_sync(0xffffffffu, s, 8);
        s += __shfl_down_sync(0xffffffffu, s, 4);
        s += __shfl_down_sync(0xffffffffu, s, 2);
        s += __shfl_down_sync(0xffffffffu, s, 1);
        if (lane == 0) red[i][wid] = s;
    }
    __syncthreads();

    if (tid < N_ITERS) {
        float t = 0.0f;
        #pragma unroll
        for (int ww = 0; ww < NTHREADS / 32; ww++) t += red[tid][ww];
        atomicAdd(&g_sums[tid], t);
    }
    __syncthreads();

    // ---- Last block computes the loss and resets state for graph replay ----
    if (tid == 0) {
        __threadfence();
        const unsigned int ticket = atomicAdd(&g_ticket, 1u);
        s_last = (ticket == TOT_BLOCKS - 1);
    }
    __syncthreads();

    if (s_last && tid == 0) {
        const float inv_n = 1.0f / (float)(NB * 3 * HW);
        float loss = 0.0f;
        #pragma unroll
        for (int k = 0; k < N_ITERS; k++) {
            const float ssum = atomicAdd(&g_sums[k], 0.0f);   // coherent read
            const float mse = ssum * inv_n;
            const float psnr = -10.0f * log10f(mse);
            const float wgt = powf(0.85f, (float)(N_ITERS - k));
            loss += psnr * wgt;
        }
        out[0] = -loss;
        #pragma unroll
        for (int k = 0; k < N_ITERS; k++) g_sums[k] = 0.0f;
        g_ticket = 0u;
        __threadfence();
    }
}

extern "C" void kernel_launch(void* const* d_in, const int* in_sizes, int n_in,
                              void* d_out, int out_size) {
    const float* flow   = (const float*)d_in[0];  // [12,4,2,384,512]
    const float* frame1 = (const float*)d_in[1];  // [4,3,384,512]
    const float* frame2 = (const float*)d_in[2];  // [4,3,384,512]
    float* out = (float*)d_out;
    (void)in_sizes; (void)n_in; (void)out_size;

    if (!g_tex_ready) create_texs();   // first (uncaptured) call only

    pack_kernel<<<(NB * HW + 255) / 256, 256>>>(frame1);

    dim3 grid(GRID_X, NB);
    warp_psnr_kernel<<<grid, NTHREADS>>>(g_texs, flow, frame2, out);
}